// round 4
// baseline (speedup 1.0000x reference)
#include <cuda_runtime.h>

#define Lc 128
#define Sc 2048
#define Bc 128
#define IGNORE_IDX (-100)
#define NT  256

// Scratch (no cudaMalloc allowed)
__device__ float g_Et[Lc * Lc];   // transposed: g_Et[j*Lc+i] = exp(trans[i*Lc+j])
__device__ float g_logz[Bc];
__device__ float g_score[Bc];

// ---------------------------------------------------------------------------
// Kernel 1: E^T = exp(T)^T, once per launch
// ---------------------------------------------------------------------------
__global__ void prep_E(const float* __restrict__ trans) {
    int idx = blockIdx.x * blockDim.x + threadIdx.x;
    if (idx < Lc * Lc) {
        int i = idx >> 7, j = idx & (Lc - 1);
        g_Et[j * Lc + i] = expf(trans[idx]);
    }
}

// packed dual-lane fp32 FMA (sm_100a+)
__device__ __forceinline__ void ffma2(unsigned long long& d,
                                      unsigned long long a,
                                      unsigned long long b) {
    asm("fma.rn.f32x2 %0, %1, %2, %0;" : "+l"(d) : "l"(a), "l"(b));
}
__device__ __forceinline__ float2 u2f2(unsigned long long v) {
    float2 f;
    f.x = __uint_as_float((unsigned)v);
    f.y = __uint_as_float((unsigned)(v >> 32));
    return f;
}

// ---------------------------------------------------------------------------
// Kernel 2: per-batch CRF forward scan + gold score.
// 256 threads: (h = tid>>7) halves split the i-reduction; h pairs share SMSPs.
// ---------------------------------------------------------------------------
__global__ __launch_bounds__(NT, 1) void crf_kernel(
    const float* __restrict__ em,     // [B,S,L] f32
    const int* __restrict__ mask,     // [B,S] int32
    const int* __restrict__ tags,     // [B,S] int32
    const float* __restrict__ trans,  // [L,L] f32
    const float* __restrict__ startt, // [L]
    const float* __restrict__ endt)   // [L]
{
    const int b   = blockIdx.x;
    const int tid = threadIdx.x;
    const int j   = tid & (Lc - 1);
    const int h   = tid >> 7;
    const int lane = tid & 31;
    const int wid  = tid >> 5;

    __shared__ __align__(16) float pbuf[2][Lc];
    __shared__ float2 tailbuf[Lc];   // .x = h1 partial, .y = s = exp(em)/r
    __shared__ float redf[8];
    __shared__ int   redi[8];

    const int*   tg  = tags + (long long)b * Sc;
    const float* emb = em   + (long long)b * Sc * Lc;
    const int*   mk  = mask + (long long)b * Sc;

    // ---------------- gold-path score (256 threads, 8 iters) ----------------
    float sc = 0.f;
    int lastIdx = -1;
    for (int t = tid; t < Sc; t += NT) {
        int tt = tg[t];
        bool v = (tt != IGNORE_IDX);
        int st = v ? tt : 0;
        if (v && t > lastIdx) lastIdx = t;
        if (t == 0) {
            if (v) sc += startt[st];
        } else if (v) {
            int tp = tg[t - 1];
            int sp = (tp != IGNORE_IDX) ? tp : 0;
            sc += trans[sp * Lc + st] + emb[(long long)t * Lc + st];
        }
    }
#pragma unroll
    for (int o = 16; o > 0; o >>= 1) {
        sc += __shfl_xor_sync(0xffffffffu, sc, o);
        lastIdx = max(lastIdx, __shfl_xor_sync(0xffffffffu, lastIdx, o));
    }
    if (lane == 0) { redf[wid] = sc; redi[wid] = lastIdx; }
    __syncthreads();
    if (tid == 0) {
        float s = 0.f; int li = -1;
#pragma unroll
        for (int w = 0; w < 8; w++) { s += redf[w]; li = max(li, redi[w]); }
        if (li >= 0) {
            int lt = tg[li];
            s += endt[(lt != IGNORE_IDX) ? lt : 0];
        }
        g_score[b] = s;
    }

    // ---------------- load packed E half-column into registers ----------------
    // thread (h,j) owns E[i][j] for i in [64h, 64h+64), packed as 32 b64 pairs
    unsigned long long Epk[32];
    {
        const ulonglong2* e2 = (const ulonglong2*)(g_Et + j * Lc + h * 64);
#pragma unroll
        for (int k = 0; k < 16; k++) {
            ulonglong2 v = e2[k];
            Epk[2 * k]     = v.x;
            Epk[2 * k + 1] = v.y;
        }
    }

    // ---------------- forward scan (prob domain) ----------------
    __syncthreads();                 // redf reuse barrier + pbuf init ordering
    if (h == 0) pbuf[0][j] = __expf(startt[j] + emb[j]);
    float C = 0.f;
    int cur = 0;
    __syncthreads();

    float em_next = emb[Lc + j];
    int   m_next  = mk[1];
    for (int t = 1; t < Sc; ++t) {
        float em_cur = em_next;
        int m = m_next;
        if (t + 1 < Sc) {
            em_next = emb[(long long)(t + 1) * Lc + j];
            m_next  = mk[t + 1];
        }
        if (m) {                       // uniform across CTA
            float r = pbuf[cur][0];    // renorm constant (valid since last bar)
            if (h == 1) {
                // off-critical-path scale: s = exp(em)/r
                tailbuf[j].y = __fdividef(__expf(em_cur), r);
            } else {
                C += __logf(r);        // uniform across h0 threads
            }

            // half dot-product: 16 LDS.128 + 32 packed FMAs
            const ulonglong2* p2 = (const ulonglong2*)(pbuf[cur] + h * 64);
            unsigned long long a0 = 0ull, a1 = 0ull;
#pragma unroll
            for (int k = 0; k < 16; k++) {
                ulonglong2 pv = p2[k];
                ffma2(a0, pv.x, Epk[2 * k]);
                ffma2(a1, pv.y, Epk[2 * k + 1]);
            }
            float2 f0 = u2f2(a0), f1 = u2f2(a1);
            float qh = (f0.x + f1.x) + (f0.y + f1.y);
            if (h == 1) tailbuf[j].x = qh;
            __syncthreads();
            if (h == 0) {
                float2 tb = tailbuf[j];
                pbuf[cur ^ 1][j] = (qh + tb.x) * tb.y;
            }
            __syncthreads();
            cur ^= 1;
        }
    }

    // ---------------- finalize log_z (h0 warps only) ----------------
    if (h == 0) {
        float v = pbuf[cur][j] * __expf(endt[j]);
#pragma unroll
        for (int o = 16; o > 0; o >>= 1) v += __shfl_xor_sync(0xffffffffu, v, o);
        if (lane == 0) redf[wid] = v;
    }
    __syncthreads();
    if (tid == 0) {
        float s = redf[0] + redf[1] + redf[2] + redf[3];
        g_logz[b] = C + logf(s);
    }
}

// ---------------------------------------------------------------------------
// Kernel 3: out = mean(log_z - score)
// ---------------------------------------------------------------------------
__global__ void final_reduce(float* __restrict__ out) {
    int j = threadIdx.x;
    float v = g_logz[j] - g_score[j];
#pragma unroll
    for (int o = 16; o > 0; o >>= 1) v += __shfl_xor_sync(0xffffffffu, v, o);
    __shared__ float red[4];
    if ((j & 31) == 0) red[j >> 5] = v;
    __syncthreads();
    if (j == 0) out[0] = (red[0] + red[1] + red[2] + red[3]) * (1.0f / (float)Bc);
}

// ---------------------------------------------------------------------------
extern "C" void kernel_launch(void* const* d_in, const int* in_sizes, int n_in,
                              void* d_out, int out_size) {
    const float* em     = (const float*)d_in[0];
    const int*   mask   = (const int*)d_in[1];
    const int*   tags   = (const int*)d_in[2];
    const float* trans  = (const float*)d_in[3];
    const float* startt = (const float*)d_in[4];
    const float* endt   = (const float*)d_in[5];
    (void)in_sizes; (void)n_in; (void)out_size;

    prep_E<<<(Lc * Lc + 255) / 256, 256>>>(trans);
    crf_kernel<<<Bc, NT>>>(em, mask, tags, trans, startt, endt);
    final_reduce<<<1, 128>>>((float*)d_out);
}

// round 7
// speedup vs baseline: 1.1375x; 1.1375x over previous
#include <cuda_runtime.h>

#define Lc 128
#define Sc 2048
#define Bc 128
#define IGNORE_IDX (-100)
#define NT  256

__device__ float g_Et[Lc * Lc];   // g_Et[j*Lc+i] = exp(trans[i*Lc+j])
__device__ float g_logz[Bc];
__device__ float g_score[Bc];

__global__ void prep_E(const float* __restrict__ trans) {
    int idx = blockIdx.x * blockDim.x + threadIdx.x;
    if (idx < Lc * Lc) {
        int i = idx >> 7, j = idx & (Lc - 1);
        g_Et[j * Lc + i] = expf(trans[idx]);
    }
}

__device__ __forceinline__ void ffma2(unsigned long long& d,
                                      unsigned long long a,
                                      unsigned long long b) {
    asm("fma.rn.f32x2 %0, %1, %2, %0;" : "+l"(d) : "l"(a), "l"(b));
}
__device__ __forceinline__ unsigned long long fadd2(unsigned long long a,
                                                    unsigned long long b) {
    unsigned long long d;
    asm("add.rn.f32x2 %0, %1, %2;" : "=l"(d) : "l"(a), "l"(b));
    return d;
}

// ---------------------------------------------------------------------------
// 2 independent batch-groups per CTA; each group = 128 threads, own named bar.
// ---------------------------------------------------------------------------
__global__ __launch_bounds__(NT, 1) void crf_kernel(
    const float* __restrict__ em,     // [B,S,L] f32
    const int* __restrict__ mask,     // [B,S] int32
    const int* __restrict__ tags,     // [B,S] int32
    const float* __restrict__ trans,  // [L,L] f32
    const float* __restrict__ startt, // [L]
    const float* __restrict__ endt)   // [L]
{
    const int tid  = threadIdx.x;
    const int g    = tid >> 7;        // batch group 0/1
    const int j    = tid & (Lc - 1);  // state column
    const int lane = tid & 31;
    const int gw   = (tid >> 5) & 3;  // warp within group
    const int b    = blockIdx.x * 2 + g;

    __shared__ __align__(16) float pbuf[2][2][Lc];  // [group][buf][state]
    __shared__ float redf[2][4];
    __shared__ int   redi[2][4];

#define GBAR() asm volatile("bar.sync %0, 128;" :: "r"(g + 1) : "memory")

    const int*   tg  = tags + (long long)b * Sc;
    const float* emb = em   + (long long)b * Sc * Lc;
    const int*   mk  = mask + (long long)b * Sc;

    // ---------------- gold-path score (per group, 16 iters) ----------------
    float sc = 0.f;
    int lastIdx = -1;
    for (int t = j; t < Sc; t += Lc) {
        int tt = tg[t];
        bool v = (tt != IGNORE_IDX);
        int st = v ? tt : 0;
        if (v && t > lastIdx) lastIdx = t;
        if (t == 0) {
            if (v) sc += startt[st];
        } else if (v) {
            int tp = tg[t - 1];
            int sp = (tp != IGNORE_IDX) ? tp : 0;
            sc += trans[sp * Lc + st] + emb[(long long)t * Lc + st];
        }
    }
#pragma unroll
    for (int o = 16; o > 0; o >>= 1) {
        sc += __shfl_xor_sync(0xffffffffu, sc, o);
        lastIdx = max(lastIdx, __shfl_xor_sync(0xffffffffu, lastIdx, o));
    }
    if (lane == 0) { redf[g][gw] = sc; redi[g][gw] = lastIdx; }
    GBAR();
    if (j == 0) {
        float s = redf[g][0] + redf[g][1] + redf[g][2] + redf[g][3];
        int li = max(max(redi[g][0], redi[g][1]), max(redi[g][2], redi[g][3]));
        if (li >= 0) {
            int lt = tg[li];
            s += endt[(lt != IGNORE_IDX) ? lt : 0];
        }
        g_score[b] = s;
    }

    // ---------------- full E column, pair-packed (64 u64 regs) ----------------
    unsigned long long Epk[64];
    {
        const ulonglong2* e2 = (const ulonglong2*)(g_Et + j * Lc);
#pragma unroll
        for (int k = 0; k < 32; k++) {
            ulonglong2 v = e2[k];
            Epk[2 * k]     = v.x;
            Epk[2 * k + 1] = v.y;
        }
    }

    // ---------------- forward scan (prob domain) ----------------
    pbuf[g][0][j] = __expf(startt[j] + emb[j]);
    float C = 0.f;
    int cur = 0;
    GBAR();

    // emissions pipeline: prefetch 2 ahead, exp 1 ahead
    float em_n1 = emb[Lc + j];                 // em[t=1]
    float em_n2 = emb[2 * Lc + j];             // em[t=2]
    int   m_n1  = mk[1];
    int   m_n2  = mk[2];
    float ex_next = __expf(em_n1);

    for (int t = 1; t < Sc; ++t) {
        float ex_cur = ex_next;
        int m = m_n1;
        em_n1 = em_n2; m_n1 = m_n2;
        if (t + 2 < Sc) {
            em_n2 = emb[(long long)(t + 2) * Lc + j];
            m_n2  = mk[t + 2];
        }
        ex_next = __expf(em_n1);               // off critical path

        if (m) {                               // uniform across group
            float r   = pbuf[g][cur][0];       // renorm const
            float inv = __fdividef(1.0f, r);   // parallel with dot
            if (gw == 0) C += __logf(r);       // only warp 0 tracks C

            const ulonglong2* p2 = (const ulonglong2*)pbuf[g][cur];
            unsigned long long acc[8];
#pragma unroll
            for (int k = 0; k < 8; k++) acc[k] = 0ull;
#pragma unroll
            for (int k = 0; k < 32; k++) {     // FULL 128-state dot (32x LDS.128)
                ulonglong2 pv = p2[k];         // broadcast LDS.128
                ffma2(acc[(2 * k) & 7],     pv.x, Epk[2 * k]);
                ffma2(acc[(2 * k + 1) & 7], pv.y, Epk[2 * k + 1]);
            }
            unsigned long long s0 = fadd2(fadd2(acc[0], acc[4]), fadd2(acc[2], acc[6]));
            unsigned long long s1 = fadd2(fadd2(acc[1], acc[5]), fadd2(acc[3], acc[7]));
            unsigned long long st = fadd2(s0, s1);
            float qlo = __uint_as_float((unsigned)st);
            float qhi = __uint_as_float((unsigned)(st >> 32));
            pbuf[g][cur ^ 1][j] = (qlo + qhi) * (ex_cur * inv);
            GBAR();
            cur ^= 1;
        }
    }

    // ---------------- finalize log_z ----------------
    float v = pbuf[g][cur][j] * __expf(endt[j]);
#pragma unroll
    for (int o = 16; o > 0; o >>= 1) v += __shfl_xor_sync(0xffffffffu, v, o);
    if (lane == 0) redf[g][gw] = v;
    GBAR();
    if (j == 0) {
        float s = redf[g][0] + redf[g][1] + redf[g][2] + redf[g][3];
        g_logz[b] = C + logf(s);
    }
#undef GBAR
}

// ---------------------------------------------------------------------------
__global__ void final_reduce(float* __restrict__ out) {
    int j = threadIdx.x;
    float v = g_logz[j] - g_score[j];
#pragma unroll
    for (int o = 16; o > 0; o >>= 1) v += __shfl_xor_sync(0xffffffffu, v, o);
    __shared__ float red[4];
    if ((j & 31) == 0) red[j >> 5] = v;
    __syncthreads();
    if (j == 0) out[0] = (red[0] + red[1] + red[2] + red[3]) * (1.0f / (float)Bc);
}

// ---------------------------------------------------------------------------
extern "C" void kernel_launch(void* const* d_in, const int* in_sizes, int n_in,
                              void* d_out, int out_size) {
    const float* em     = (const float*)d_in[0];
    const int*   mask   = (const int*)d_in[1];
    const int*   tags   = (const int*)d_in[2];
    const float* trans  = (const float*)d_in[3];
    const float* startt = (const float*)d_in[4];
    const float* endt   = (const float*)d_in[5];
    (void)in_sizes; (void)n_in; (void)out_size;

    prep_E<<<(Lc * Lc + 255) / 256, 256>>>(trans);
    crf_kernel<<<Bc / 2, NT>>>(em, mask, tags, trans, startt, endt);
    final_reduce<<<1, 128>>>((float*)d_out);
}

// round 8
// speedup vs baseline: 1.1722x; 1.0305x over previous
#include <cuda_runtime.h>

#define Lc 128
#define Sc 2048
#define Bc 128
#define IGNORE_IDX (-100)
#define NT  256

__device__ float g_Et[Lc * Lc];   // g_Et[j*Lc+i] = exp(trans[i*Lc+j])
__device__ float g_logz[Bc];
__device__ float g_score[Bc];

__global__ void prep_E(const float* __restrict__ trans) {
    int idx = blockIdx.x * blockDim.x + threadIdx.x;
    if (idx < Lc * Lc) {
        int i = idx >> 7, j = idx & (Lc - 1);
        g_Et[j * Lc + i] = expf(trans[idx]);
    }
}

__device__ __forceinline__ void ffma2(unsigned long long& d,
                                      unsigned long long a,
                                      unsigned long long b) {
    asm("fma.rn.f32x2 %0, %1, %2, %0;" : "+l"(d) : "l"(a), "l"(b));
}
__device__ __forceinline__ unsigned long long fadd2(unsigned long long a,
                                                    unsigned long long b) {
    unsigned long long d;
    asm("add.rn.f32x2 %0, %1, %2;" : "=l"(d) : "l"(a), "l"(b));
    return d;
}

// ---------------------------------------------------------------------------
// 1 batch per CTA, 256 threads. Warp w, lane l:
//   j = 16w + (l&15)  (state column), h = l>>4 (i-half).
// Each thread: 64-length dot; halves combined by shfl_xor(16) — no extra bar.
// ---------------------------------------------------------------------------
__global__ __launch_bounds__(NT, 1) void crf_kernel(
    const float* __restrict__ em,     // [B,S,L] f32
    const int* __restrict__ mask,     // [B,S] int32
    const int* __restrict__ tags,     // [B,S] int32
    const float* __restrict__ trans,  // [L,L] f32
    const float* __restrict__ startt, // [L]
    const float* __restrict__ endt)   // [L]
{
    const int b    = blockIdx.x;
    const int tid  = threadIdx.x;
    const int w    = tid >> 5;
    const int l    = tid & 31;
    const int j    = (w << 4) | (l & 15);
    const int h    = l >> 4;

    __shared__ __align__(16) float pbuf[2][Lc];
    __shared__ float redf[8];
    __shared__ int   redi[8];

    const int*   tg  = tags + (long long)b * Sc;
    const float* emb = em   + (long long)b * Sc * Lc;
    const int*   mk  = mask + (long long)b * Sc;

    // ---------------- gold-path score (256 threads, 8 iters) ----------------
    float sc = 0.f;
    int lastIdx = -1;
    for (int t = tid; t < Sc; t += NT) {
        int tt = tg[t];
        bool v = (tt != IGNORE_IDX);
        int st = v ? tt : 0;
        if (v && t > lastIdx) lastIdx = t;
        if (t == 0) {
            if (v) sc += startt[st];
        } else if (v) {
            int tp = tg[t - 1];
            int sp = (tp != IGNORE_IDX) ? tp : 0;
            sc += trans[sp * Lc + st] + emb[(long long)t * Lc + st];
        }
    }
#pragma unroll
    for (int o = 16; o > 0; o >>= 1) {
        sc += __shfl_xor_sync(0xffffffffu, sc, o);
        lastIdx = max(lastIdx, __shfl_xor_sync(0xffffffffu, lastIdx, o));
    }
    if (l == 0) { redf[w] = sc; redi[w] = lastIdx; }
    __syncthreads();
    if (tid == 0) {
        float s = 0.f; int li = -1;
#pragma unroll
        for (int k = 0; k < 8; k++) { s += redf[k]; li = max(li, redi[k]); }
        if (li >= 0) {
            int lt = tg[li];
            s += endt[(lt != IGNORE_IDX) ? lt : 0];
        }
        g_score[b] = s;
    }

    // ---------------- E half-column, pair-packed (32 u64 regs) ----------------
    unsigned long long Epk[32];
    {
        const ulonglong2* e2 = (const ulonglong2*)(g_Et + j * Lc + 64 * h);
#pragma unroll
        for (int k = 0; k < 16; k++) {
            ulonglong2 v = e2[k];
            Epk[2 * k]     = v.x;
            Epk[2 * k + 1] = v.y;
        }
    }

    // ---------------- forward scan (prob domain) ----------------
    __syncthreads();                         // redf reuse fence
    if (l < 16) pbuf[0][j] = __expf(startt[j] + emb[j]);
    float C = 0.f;
    int cur = 0;
    __syncthreads();

    // emissions pipeline: prefetch 3 ahead, exp 1 ahead
    float e1 = emb[Lc + j];
    float e2 = emb[2 * Lc + j];
    float e3 = emb[3 * Lc + j];
    int   m1 = mk[1], m2 = mk[2], m3 = mk[3];
    float ex_next = __expf(e1);

    for (int t = 1; t < Sc; ++t) {
        float ex_cur = ex_next;
        int m = m1;
        e1 = e2; m1 = m2;
        e2 = e3; m2 = m3;
        if (t + 3 < Sc) {
            e3 = emb[(long long)(t + 3) * Lc + j];
            m3 = mk[t + 3];
        }
        ex_next = __expf(e1);                // off critical path

        if (m) {                             // uniform across CTA
            float r   = pbuf[cur][0];        // renorm const
            float inv = __fdividef(1.0f, r); // hidden under the dot
            if (tid == 0) C += __logf(r);

            const ulonglong2* p2 = (const ulonglong2*)(pbuf[cur] + 64 * h);
            unsigned long long a0 = 0ull, a1 = 0ull, a2 = 0ull, a3 = 0ull;
#pragma unroll
            for (int k = 0; k < 16; k += 2) {
                ulonglong2 pv0 = p2[k];
                ulonglong2 pv1 = p2[k + 1];
                ffma2(a0, pv0.x, Epk[2 * k]);
                ffma2(a1, pv0.y, Epk[2 * k + 1]);
                ffma2(a2, pv1.x, Epk[2 * k + 2]);
                ffma2(a3, pv1.y, Epk[2 * k + 3]);
            }
            unsigned long long st = fadd2(fadd2(a0, a2), fadd2(a1, a3));
            float q = __uint_as_float((unsigned)st) +
                      __uint_as_float((unsigned)(st >> 32));
            q += __shfl_xor_sync(0xffffffffu, q, 16);   // combine i-halves
            if (l < 16) pbuf[cur ^ 1][j] = q * (ex_cur * inv);
            __syncthreads();
            cur ^= 1;
        }
    }

    // ---------------- finalize log_z ----------------
    if (tid < Lc) {
        float v = pbuf[cur][tid] * __expf(endt[tid]);
#pragma unroll
        for (int o = 16; o > 0; o >>= 1) v += __shfl_xor_sync(0xffffffffu, v, o);
        if ((tid & 31) == 0) redf[tid >> 5] = v;
    }
    __syncthreads();
    if (tid == 0) {
        float s = redf[0] + redf[1] + redf[2] + redf[3];
        g_logz[b] = C + logf(s);
    }
}

// ---------------------------------------------------------------------------
__global__ void final_reduce(float* __restrict__ out) {
    int j = threadIdx.x;
    float v = g_logz[j] - g_score[j];
#pragma unroll
    for (int o = 16; o > 0; o >>= 1) v += __shfl_xor_sync(0xffffffffu, v, o);
    __shared__ float red[4];
    if ((j & 31) == 0) red[j >> 5] = v;
    __syncthreads();
    if (j == 0) out[0] = (red[0] + red[1] + red[2] + red[3]) * (1.0f / (float)Bc);
}

// ---------------------------------------------------------------------------
extern "C" void kernel_launch(void* const* d_in, const int* in_sizes, int n_in,
                              void* d_out, int out_size) {
    const float* em     = (const float*)d_in[0];
    const int*   mask   = (const int*)d_in[1];
    const int*   tags   = (const int*)d_in[2];
    const float* trans  = (const float*)d_in[3];
    const float* startt = (const float*)d_in[4];
    const float* endt   = (const float*)d_in[5];
    (void)in_sizes; (void)n_in; (void)out_size;

    prep_E<<<(Lc * Lc + 255) / 256, 256>>>(trans);
    crf_kernel<<<Bc, NT>>>(em, mask, tags, trans, startt, endt);
    final_reduce<<<1, 128>>>((float*)d_out);
}

// round 9
// speedup vs baseline: 1.6539x; 1.4109x over previous
#include <cuda_runtime.h>

#define Lc 128
#define Sc 2048
#define Bc 128
#define IGNORE_IDX (-100)
#define NT  256
#define PD  6                     // emissions prefetch depth (steps of slack)

__device__ float g_Et[Lc * Lc];   // g_Et[j*Lc+i] = exp(trans[i*Lc+j])
__device__ float g_logz[Bc];
__device__ float g_score[Bc];

__global__ void prep_E(const float* __restrict__ trans) {
    int idx = blockIdx.x * blockDim.x + threadIdx.x;
    if (idx < Lc * Lc) {
        int i = idx >> 7, j = idx & (Lc - 1);
        g_Et[j * Lc + i] = expf(trans[idx]);
    }
}

__device__ __forceinline__ void ffma2(unsigned long long& d,
                                      unsigned long long a,
                                      unsigned long long b) {
    asm("fma.rn.f32x2 %0, %1, %2, %0;" : "+l"(d) : "l"(a), "l"(b));
}
__device__ __forceinline__ unsigned long long fadd2(unsigned long long a,
                                                    unsigned long long b) {
    unsigned long long d;
    asm("add.rn.f32x2 %0, %1, %2;" : "=l"(d) : "l"(a), "l"(b));
    return d;
}

// ---------------------------------------------------------------------------
// 1 batch per CTA, 256 threads. Warp w, lane l:
//   j = 16w + (l&15) (state column), h = l>>4 (i-half).
// 64-length dot per thread; halves combined via shfl_xor(16). One bar/step.
// Emissions prefetched PD steps ahead (ring, compile-time indexed via unroll).
// ---------------------------------------------------------------------------
__global__ __launch_bounds__(NT, 1) void crf_kernel(
    const float* __restrict__ em,     // [B,S,L] f32
    const int* __restrict__ mask,     // [B,S] int32
    const int* __restrict__ tags,     // [B,S] int32
    const float* __restrict__ trans,  // [L,L] f32
    const float* __restrict__ startt, // [L]
    const float* __restrict__ endt)   // [L]
{
    const int b    = blockIdx.x;
    const int tid  = threadIdx.x;
    const int w    = tid >> 5;
    const int l    = tid & 31;
    const int j    = (w << 4) | (l & 15);
    const int h    = l >> 4;

    __shared__ __align__(16) float pbuf[2][Lc];
    __shared__ float redf[8];
    __shared__ int   redi[8];

    const int*   tg  = tags + (long long)b * Sc;
    const float* emb = em   + (long long)b * Sc * Lc;
    const int*   mk  = mask + (long long)b * Sc;

    // ---------------- gold-path score (256 threads, 8 iters) ----------------
    float sc = 0.f;
    int lastIdx = -1;
    for (int t = tid; t < Sc; t += NT) {
        int tt = tg[t];
        bool v = (tt != IGNORE_IDX);
        int st = v ? tt : 0;
        if (v && t > lastIdx) lastIdx = t;
        if (t == 0) {
            if (v) sc += startt[st];
        } else if (v) {
            int tp = tg[t - 1];
            int sp = (tp != IGNORE_IDX) ? tp : 0;
            sc += trans[sp * Lc + st] + emb[(long long)t * Lc + st];
        }
    }
#pragma unroll
    for (int o = 16; o > 0; o >>= 1) {
        sc += __shfl_xor_sync(0xffffffffu, sc, o);
        lastIdx = max(lastIdx, __shfl_xor_sync(0xffffffffu, lastIdx, o));
    }
    if (l == 0) { redf[w] = sc; redi[w] = lastIdx; }
    __syncthreads();
    if (tid == 0) {
        float s = 0.f; int li = -1;
#pragma unroll
        for (int k = 0; k < 8; k++) { s += redf[k]; li = max(li, redi[k]); }
        if (li >= 0) {
            int lt = tg[li];
            s += endt[(lt != IGNORE_IDX) ? lt : 0];
        }
        g_score[b] = s;
    }

    // ---------------- E half-column, pair-packed (32 u64 regs) ----------------
    unsigned long long Epk[32];
    {
        const ulonglong2* e2 = (const ulonglong2*)(g_Et + j * Lc + 64 * h);
#pragma unroll
        for (int k = 0; k < 16; k++) {
            ulonglong2 v = e2[k];
            Epk[2 * k]     = v.x;
            Epk[2 * k + 1] = v.y;
        }
    }

    // ---------------- forward scan (prob domain) ----------------
    __syncthreads();                         // redf reuse fence
    if (l < 16) pbuf[0][j] = __expf(startt[j] + emb[j]);
    float C = 0.f;
    int cur = 0;
    __syncthreads();

    // Prefetch ring: slot (t-1)%PD holds em[t], mk[t]
    float er[PD];
    int   mr[PD];
#pragma unroll
    for (int d = 0; d < PD; d++) {
        er[d] = emb[(long long)(1 + d) * Lc + j];
        mr[d] = mk[1 + d];
    }

#pragma unroll 6
    for (int t = 1; t < Sc; ++t) {
        const int s = (t - 1) % PD;          // compile-time under unroll
        float em_c = er[s];
        int   m    = mr[s];
        if (t + PD < Sc) {                   // refill PD ahead
            er[s] = emb[(long long)(t + PD) * Lc + j];
            mr[s] = mk[t + PD];
        }

        if (m) {                             // uniform across CTA
            float r   = pbuf[cur][0];        // renorm const (broadcast LDS)
            float inv = __fdividef(1.0f, r); // hidden under dot
            float exc = __expf(em_c);        // hidden under dot
            C += __logf(r);                  // all threads, identical value

            const ulonglong2* p2 = (const ulonglong2*)(pbuf[cur] + 64 * h);
            unsigned long long a0 = 0ull, a1 = 0ull, a2 = 0ull, a3 = 0ull;
#pragma unroll
            for (int k = 0; k < 16; k += 2) {
                ulonglong2 pv0 = p2[k];
                ulonglong2 pv1 = p2[k + 1];
                ffma2(a0, pv0.x, Epk[2 * k]);
                ffma2(a1, pv0.y, Epk[2 * k + 1]);
                ffma2(a2, pv1.x, Epk[2 * k + 2]);
                ffma2(a3, pv1.y, Epk[2 * k + 3]);
            }
            unsigned long long sm = fadd2(fadd2(a0, a2), fadd2(a1, a3));
            float q = __uint_as_float((unsigned)sm) +
                      __uint_as_float((unsigned)(sm >> 32));
            q += __shfl_xor_sync(0xffffffffu, q, 16);   // combine i-halves
            if (l < 16) pbuf[cur ^ 1][j] = q * (exc * inv);
            __syncthreads();
            cur ^= 1;
        }
    }

    // ---------------- finalize log_z ----------------
    if (tid < Lc) {
        float v = pbuf[cur][tid] * __expf(endt[tid]);
#pragma unroll
        for (int o = 16; o > 0; o >>= 1) v += __shfl_xor_sync(0xffffffffu, v, o);
        if ((tid & 31) == 0) redf[tid >> 5] = v;
    }
    __syncthreads();
    if (tid == 0) {
        float s = redf[0] + redf[1] + redf[2] + redf[3];
        g_logz[b] = C + logf(s);
    }
}

// ---------------------------------------------------------------------------
__global__ void final_reduce(float* __restrict__ out) {
    int j = threadIdx.x;
    float v = g_logz[j] - g_score[j];
#pragma unroll
    for (int o = 16; o > 0; o >>= 1) v += __shfl_xor_sync(0xffffffffu, v, o);
    __shared__ float red[4];
    if ((j & 31) == 0) red[j >> 5] = v;
    __syncthreads();
    if (j == 0) out[0] = (red[0] + red[1] + red[2] + red[3]) * (1.0f / (float)Bc);
}

// ---------------------------------------------------------------------------
extern "C" void kernel_launch(void* const* d_in, const int* in_sizes, int n_in,
                              void* d_out, int out_size) {
    const float* em     = (const float*)d_in[0];
    const int*   mask   = (const int*)d_in[1];
    const int*   tags   = (const int*)d_in[2];
    const float* trans  = (const float*)d_in[3];
    const float* startt = (const float*)d_in[4];
    const float* endt   = (const float*)d_in[5];
    (void)in_sizes; (void)n_in; (void)out_size;

    prep_E<<<(Lc * Lc + 255) / 256, 256>>>(trans);
    crf_kernel<<<Bc, NT>>>(em, mask, tags, trans, startt, endt);
    final_reduce<<<1, 128>>>((float*)d_out);
}

// round 10
// speedup vs baseline: 2.5151x; 1.5208x over previous
#include <cuda_runtime.h>

#define Lc 128
#define Sc 2048
#define Mh (Sc / 2)               // split point: fwd covers t=1..Mh, bwd t=Sc-1..Mh+1
#define Bc 128
#define IGNORE_IDX (-100)
#define NT  256
#define PD  6                     // prefetch depth (steps of slack)

__device__ float g_E [Lc * Lc];   // row-major: g_E[i*Lc+j]  = exp(trans[i][j])
__device__ float g_Et[Lc * Lc];   // transposed: g_Et[j*Lc+i] = exp(trans[i][j])
__device__ float g_aM[Bc * Lc];   // scaled forward vector at t=Mh
__device__ float g_bM[Bc * Lc];   // scaled backward vector at t=Mh
__device__ float g_Cf[Bc], g_Cb[Bc];
__device__ float g_logz[Bc];
__device__ float g_score[Bc];

__global__ void prep_E(const float* __restrict__ trans) {
    int idx = blockIdx.x * blockDim.x + threadIdx.x;
    if (idx < Lc * Lc) {
        int i = idx >> 7, j = idx & (Lc - 1);
        float v = expf(trans[idx]);
        g_E[idx] = v;
        g_Et[j * Lc + i] = v;
    }
}

__device__ __forceinline__ void ffma2(unsigned long long& d,
                                      unsigned long long a,
                                      unsigned long long b) {
    asm("fma.rn.f32x2 %0, %1, %2, %0;" : "+l"(d) : "l"(a), "l"(b));
}
__device__ __forceinline__ unsigned long long fadd2(unsigned long long a,
                                                    unsigned long long b) {
    unsigned long long d;
    asm("add.rn.f32x2 %0, %1, %2;" : "=l"(d) : "l"(a), "l"(b));
    return d;
}

// 64-length dot of smem half against register-packed E half, combined over h
// via shfl_xor(16). Returns full 128-dot in every lane.
__device__ __forceinline__ float dot128(const float* base, int h,
                                        const unsigned long long* Epk) {
    const ulonglong2* p2 = (const ulonglong2*)(base + 64 * h);
    unsigned long long a0 = 0ull, a1 = 0ull, a2 = 0ull, a3 = 0ull;
#pragma unroll
    for (int k = 0; k < 16; k += 2) {
        ulonglong2 pv0 = p2[k];
        ulonglong2 pv1 = p2[k + 1];
        ffma2(a0, pv0.x, Epk[2 * k]);
        ffma2(a1, pv0.y, Epk[2 * k + 1]);
        ffma2(a2, pv1.x, Epk[2 * k + 2]);
        ffma2(a3, pv1.y, Epk[2 * k + 3]);
    }
    unsigned long long sm = fadd2(fadd2(a0, a2), fadd2(a1, a3));
    float q = __uint_as_float((unsigned)sm) +
              __uint_as_float((unsigned)(sm >> 32));
    q += __shfl_xor_sync(0xffffffffu, q, 16);
    return q;
}

// ---------------------------------------------------------------------------
// 2 CTAs per batch: dir 0 = forward (steps 1..Mh, + gold score),
//                   dir 1 = backward (steps Sc-1..Mh+1).
// Per CTA: 256 threads; warp w lane l: j = 16w + (l&15), h = l>>4.
// ---------------------------------------------------------------------------
__global__ __launch_bounds__(NT, 2) void crf_scan(
    const float* __restrict__ em,     // [B,S,L] f32
    const int* __restrict__ mask,     // [B,S] int32
    const int* __restrict__ tags,     // [B,S] int32
    const float* __restrict__ trans,  // [L,L] f32
    const float* __restrict__ startt, // [L]
    const float* __restrict__ endt)   // [L]
{
    const int c   = blockIdx.x;
    const int b   = c >> 1;
    const int dir = c & 1;
    const int tid = threadIdx.x;
    const int w   = tid >> 5;
    const int l   = tid & 31;
    const int j   = (w << 4) | (l & 15);
    const int h   = l >> 4;

    __shared__ __align__(16) float pbuf[2][Lc];   // fwd: a ; bwd: d = em⊙β
    __shared__ float bbuf[Lc];                    // bwd: plain β
    __shared__ float redf[8];
    __shared__ int   redi[8];

    const int*   tg  = tags + (long long)b * Sc;
    const float* emb = em   + (long long)b * Sc * Lc;
    const int*   mk  = mask + (long long)b * Sc;

    float er[PD];
    int   mr[PD];
    float C = 0.f;
    int cur = 0;

    if (dir == 0) {
        // ---------------- gold-path score ----------------
        float sc = 0.f;
        int lastIdx = -1;
        for (int t = tid; t < Sc; t += NT) {
            int tt = tg[t];
            bool v = (tt != IGNORE_IDX);
            int st = v ? tt : 0;
            if (v && t > lastIdx) lastIdx = t;
            if (t == 0) {
                if (v) sc += startt[st];
            } else if (v) {
                int tp = tg[t - 1];
                int sp = (tp != IGNORE_IDX) ? tp : 0;
                sc += trans[sp * Lc + st] + emb[(long long)t * Lc + st];
            }
        }
#pragma unroll
        for (int o = 16; o > 0; o >>= 1) {
            sc += __shfl_xor_sync(0xffffffffu, sc, o);
            lastIdx = max(lastIdx, __shfl_xor_sync(0xffffffffu, lastIdx, o));
        }
        if (l == 0) { redf[w] = sc; redi[w] = lastIdx; }
        __syncthreads();
        if (tid == 0) {
            float s = 0.f; int li = -1;
#pragma unroll
            for (int k = 0; k < 8; k++) { s += redf[k]; li = max(li, redi[k]); }
            if (li >= 0) {
                int lt = tg[li];
                s += endt[(lt != IGNORE_IDX) ? lt : 0];
            }
            g_score[b] = s;
        }

        // E column j (transposed layout), packed
        unsigned long long Epk[32];
        {
            const ulonglong2* e2 = (const ulonglong2*)(g_Et + j * Lc + 64 * h);
#pragma unroll
            for (int k = 0; k < 16; k++) {
                ulonglong2 v = e2[k];
                Epk[2 * k] = v.x; Epk[2 * k + 1] = v.y;
            }
        }

        __syncthreads();
        if (l < 16) pbuf[0][j] = __expf(startt[j] + emb[j]);
        __syncthreads();

#pragma unroll
        for (int d = 0; d < PD; d++) {
            er[d] = emb[(long long)(1 + d) * Lc + j];
            mr[d] = mk[1 + d];
        }

#pragma unroll 6
        for (int t = 1; t <= Mh; ++t) {
            const int s = (t - 1) % PD;
            float em_c = er[s];
            int   m    = mr[s];
            er[s] = emb[(long long)(t + PD) * Lc + j];   // t+PD <= Mh+PD < Sc
            mr[s] = mk[t + PD];

            if (m) {
                float r   = pbuf[cur][0];
                float inv = __fdividef(1.0f, r);
                float exc = __expf(em_c);
                C += __logf(r);
                float q = dot128(pbuf[cur], h, Epk);
                if (l < 16) pbuf[cur ^ 1][j] = q * (exc * inv);
                __syncthreads();
                cur ^= 1;
            }
        }
        if (l < 16) g_aM[b * Lc + j] = pbuf[cur][j];
        if (tid == 0) g_Cf[b] = C;

    } else {
        // E row j (row-major layout), packed
        unsigned long long Epk[32];
        {
            const ulonglong2* e2 = (const ulonglong2*)(g_E + j * Lc + 64 * h);
#pragma unroll
            for (int k = 0; k < 16; k++) {
                ulonglong2 v = e2[k];
                Epk[2 * k] = v.x; Epk[2 * k + 1] = v.y;
            }
        }

        // init at t = Sc-1: β = exp(end), d = exp(em + end)
        if (l < 16) {
            float ee = __expf(endt[j]);
            bbuf[j]    = ee;
            pbuf[0][j] = __expf(emb[(long long)(Sc - 1) * Lc + j]) * ee;
        }
        __syncthreads();

        // rings: step s uses em[2046-s] (= em_{t-1}) and mask[2047-s] (= mask_t)
#pragma unroll
        for (int d = 0; d < PD; d++) {
            er[d] = emb[(long long)(Sc - 2 - d) * Lc + j];
            mr[d] = mk[Sc - 1 - d];
        }

#pragma unroll 6
        for (int s = 0; s < Mh - 1; ++s) {           // t = Sc-1-s, down to Mh+1
            const int sl = s % PD;
            float em_c = er[sl];                      // em_{t-1}
            int   m    = mr[sl];                      // mask_t
            int tp = Sc - 2 - (s + PD);               // refill (>= Mh-PD-1 >= 0)
            er[sl] = emb[(long long)tp * Lc + j];
            mr[sl] = mk[tp + 1];

            bool last = (s == Mh - 2);                // producing β at t-1 = Mh
            if (m) {
                float r   = pbuf[cur][0];
                float inv = __fdividef(1.0f, r);
                float exc = __expf(em_c);
                C += __logf(r);
                float q = dot128(pbuf[cur], h, Epk);  // = (E·d)[j], unscaled
                if (l < 16) {
                    float bn = q * inv;
                    bbuf[j] = bn;
                    pbuf[cur ^ 1][j] = last ? bn : bn * exc;
                }
                __syncthreads();
                cur ^= 1;
            } else if (!last) {
                // identity step: refold d with em_{t-1}
                if (l < 16) pbuf[cur][j] = bbuf[j] * __expf(em_c);
                __syncthreads();
            }
        }
        if (l < 16) g_bM[b * Lc + j] = bbuf[j];
        if (tid == 0) g_Cb[b] = C;
    }
}

// ---------------------------------------------------------------------------
// combine: log_z[b] = Cf + Cb + log( sum_j aM[j]*bM[j] )
// ---------------------------------------------------------------------------
__global__ void combine(void) {
    int b = blockIdx.x, tid = threadIdx.x;
    float v = g_aM[b * Lc + tid] * g_bM[b * Lc + tid];
#pragma unroll
    for (int o = 16; o > 0; o >>= 1) v += __shfl_xor_sync(0xffffffffu, v, o);
    __shared__ float red[4];
    if ((tid & 31) == 0) red[tid >> 5] = v;
    __syncthreads();
    if (tid == 0)
        g_logz[b] = g_Cf[b] + g_Cb[b] + logf(red[0] + red[1] + red[2] + red[3]);
}

__global__ void final_reduce(float* __restrict__ out) {
    int j = threadIdx.x;
    float v = g_logz[j] - g_score[j];
#pragma unroll
    for (int o = 16; o > 0; o >>= 1) v += __shfl_xor_sync(0xffffffffu, v, o);
    __shared__ float red[4];
    if ((j & 31) == 0) red[j >> 5] = v;
    __syncthreads();
    if (j == 0) out[0] = (red[0] + red[1] + red[2] + red[3]) * (1.0f / (float)Bc);
}

// ---------------------------------------------------------------------------
extern "C" void kernel_launch(void* const* d_in, const int* in_sizes, int n_in,
                              void* d_out, int out_size) {
    const float* em     = (const float*)d_in[0];
    const int*   mask   = (const int*)d_in[1];
    const int*   tags   = (const int*)d_in[2];
    const float* trans  = (const float*)d_in[3];
    const float* startt = (const float*)d_in[4];
    const float* endt   = (const float*)d_in[5];
    (void)in_sizes; (void)n_in; (void)out_size;

    prep_E<<<(Lc * Lc + 255) / 256, 256>>>(trans);
    crf_scan<<<2 * Bc, NT>>>(em, mask, tags, trans, startt, endt);
    combine<<<Bc, Lc>>>();
    final_reduce<<<1, 128>>>((float*)d_out);
}

// round 11
// speedup vs baseline: 2.5559x; 1.0162x over previous
#include <cuda_runtime.h>

#define Lc 128
#define Sc 2048
#define Mh (Sc / 2)               // split: fwd covers t=1..Mh, bwd t=Sc-1..Mh+1
#define Bc 128
#define IGNORE_IDX (-100)
#define NT  256
#define PD  6                     // prefetch depth (steps of slack)

__device__ float g_E [Lc * Lc];   // row-major: exp(trans[i][j])
__device__ float g_Et[Lc * Lc];   // transposed
__device__ float g_aM[Bc * Lc];
__device__ float g_bM[Bc * Lc];
__device__ float g_Cf[Bc], g_Cb[Bc];
__device__ float g_logz[Bc];
__device__ float g_score[Bc];

__global__ void prep_E(const float* __restrict__ trans) {
    int idx = blockIdx.x * blockDim.x + threadIdx.x;
    if (idx < Lc * Lc) {
        int i = idx >> 7, j = idx & (Lc - 1);
        float v = expf(trans[idx]);
        g_E[idx] = v;
        g_Et[j * Lc + i] = v;
    }
}

__device__ __forceinline__ void ffma2(unsigned long long& d,
                                      unsigned long long a,
                                      unsigned long long b) {
    asm("fma.rn.f32x2 %0, %1, %2, %0;" : "+l"(d) : "l"(a), "l"(b));
}
__device__ __forceinline__ unsigned long long fadd2(unsigned long long a,
                                                    unsigned long long b) {
    unsigned long long d;
    asm("add.rn.f32x2 %0, %1, %2;" : "=l"(d) : "l"(a), "l"(b));
    return d;
}

// exact power-of-two renorm: r -> (e = floor(log2 r), inv = 2^-e)
__device__ __forceinline__ float exp_strip(float r, int& e_out) {
    unsigned bits = __float_as_uint(r);
    int be = (int)(bits >> 23);          // biased exponent (r > 0 always)
    e_out = be - 127;
    return __uint_as_float((unsigned)(254 - be) << 23);   // 2^{-(be-127)}
}

// 64-length dot of smem half vs register-packed E half; full 128-dot via shfl.
__device__ __forceinline__ float dot128(const float* base, int h,
                                        const unsigned long long* Epk) {
    const ulonglong2* p2 = (const ulonglong2*)(base + 64 * h);
    unsigned long long a0 = 0ull, a1 = 0ull, a2 = 0ull, a3 = 0ull;
#pragma unroll
    for (int k = 0; k < 16; k += 2) {
        ulonglong2 pv0 = p2[k];
        ulonglong2 pv1 = p2[k + 1];
        ffma2(a0, pv0.x, Epk[2 * k]);
        ffma2(a1, pv0.y, Epk[2 * k + 1]);
        ffma2(a2, pv1.x, Epk[2 * k + 2]);
        ffma2(a3, pv1.y, Epk[2 * k + 3]);
    }
    unsigned long long sm = fadd2(fadd2(a0, a2), fadd2(a1, a3));
    float q = __uint_as_float((unsigned)sm) +
              __uint_as_float((unsigned)(sm >> 32));
    q += __shfl_xor_sync(0xffffffffu, q, 16);
    return q;
}

// ---------------------------------------------------------------------------
// 2 CTAs per batch: dir 0 = forward (+ gold score), dir 1 = backward.
// warp w lane l: j = 16w + (l&15), h = l>>4.
// ---------------------------------------------------------------------------
__global__ __launch_bounds__(NT, 2) void crf_scan(
    const float* __restrict__ em,
    const int* __restrict__ mask,
    const int* __restrict__ tags,
    const float* __restrict__ trans,
    const float* __restrict__ startt,
    const float* __restrict__ endt)
{
    const int c   = blockIdx.x;
    const int b   = c >> 1;
    const int dir = c & 1;
    const int tid = threadIdx.x;
    const int w   = tid >> 5;
    const int l   = tid & 31;
    const int j   = (w << 4) | (l & 15);
    const int h   = l >> 4;

    __shared__ __align__(16) float pbuf[2][Lc];
    __shared__ float bbuf[Lc];
    __shared__ float redf[8];
    __shared__ int   redi[8];

    const int*   tg  = tags + (long long)b * Sc;
    const float* emb = em   + (long long)b * Sc * Lc;
    const int*   mk  = mask + (long long)b * Sc;

    float er[PD];
    int   mr[PD];
    int   Ci = 0;                 // exact: sum of stripped exponents
    int   cur = 0;

    if (dir == 0) {
        // ---------------- gold-path score ----------------
        float sc = 0.f;
        int lastIdx = -1;
        for (int t = tid; t < Sc; t += NT) {
            int tt = tg[t];
            bool v = (tt != IGNORE_IDX);
            int st = v ? tt : 0;
            if (v && t > lastIdx) lastIdx = t;
            if (t == 0) {
                if (v) sc += startt[st];
            } else if (v) {
                int tp = tg[t - 1];
                int sp = (tp != IGNORE_IDX) ? tp : 0;
                sc += trans[sp * Lc + st] + emb[(long long)t * Lc + st];
            }
        }
#pragma unroll
        for (int o = 16; o > 0; o >>= 1) {
            sc += __shfl_xor_sync(0xffffffffu, sc, o);
            lastIdx = max(lastIdx, __shfl_xor_sync(0xffffffffu, lastIdx, o));
        }
        if (l == 0) { redf[w] = sc; redi[w] = lastIdx; }
        __syncthreads();
        if (tid == 0) {
            float s = 0.f; int li = -1;
#pragma unroll
            for (int k = 0; k < 8; k++) { s += redf[k]; li = max(li, redi[k]); }
            if (li >= 0) {
                int lt = tg[li];
                s += endt[(lt != IGNORE_IDX) ? lt : 0];
            }
            g_score[b] = s;
        }

        unsigned long long Epk[32];
        {
            const ulonglong2* e2 = (const ulonglong2*)(g_Et + j * Lc + 64 * h);
#pragma unroll
            for (int k = 0; k < 16; k++) {
                ulonglong2 v = e2[k];
                Epk[2 * k] = v.x; Epk[2 * k + 1] = v.y;
            }
        }

        __syncthreads();
        if (l < 16) pbuf[0][j] = __expf(startt[j] + emb[j]);
        __syncthreads();

#pragma unroll
        for (int d = 0; d < PD; d++) {
            er[d] = emb[(long long)(1 + d) * Lc + j];
            mr[d] = mk[1 + d];
        }

#pragma unroll 6
        for (int t = 1; t <= Mh; ++t) {
            const int s = (t - 1) % PD;
            float em_c = er[s];
            int   m    = mr[s];
            er[s] = emb[(long long)(t + PD) * Lc + j];
            mr[s] = mk[t + PD];

            if (m) {
                int e;
                float inv = exp_strip(pbuf[cur][0], e);
                Ci += e;
                float sfac = __expf(em_c) * inv;        // hidden under dot
                float q = dot128(pbuf[cur], h, Epk);
                if (l < 16) pbuf[cur ^ 1][j] = q * sfac;
                __syncthreads();
                cur ^= 1;
            }
        }
        if (l < 16) g_aM[b * Lc + j] = pbuf[cur][j];
        if (tid == 0) g_Cf[b] = (float)((double)Ci * 0.6931471805599453);

    } else {
        unsigned long long Epk[32];
        {
            const ulonglong2* e2 = (const ulonglong2*)(g_E + j * Lc + 64 * h);
#pragma unroll
            for (int k = 0; k < 16; k++) {
                ulonglong2 v = e2[k];
                Epk[2 * k] = v.x; Epk[2 * k + 1] = v.y;
            }
        }

        if (l < 16) {
            float ee = __expf(endt[j]);
            bbuf[j]    = ee;
            pbuf[0][j] = __expf(emb[(long long)(Sc - 1) * Lc + j]) * ee;
        }
        __syncthreads();

#pragma unroll
        for (int d = 0; d < PD; d++) {
            er[d] = emb[(long long)(Sc - 2 - d) * Lc + j];
            mr[d] = mk[Sc - 1 - d];
        }

#pragma unroll 6
        for (int s = 0; s < Mh - 1; ++s) {           // t = Sc-1-s down to Mh+1
            const int sl = s % PD;
            float em_c = er[sl];                      // em_{t-1}
            int   m    = mr[sl];                      // mask_t
            int tp = Sc - 2 - (s + PD);
            er[sl] = emb[(long long)tp * Lc + j];
            mr[sl] = mk[tp + 1];

            bool last = (s == Mh - 2);
            if (m) {
                int e;
                float inv = exp_strip(pbuf[cur][0], e);
                Ci += e;
                float exc = __expf(em_c);
                float q = dot128(pbuf[cur], h, Epk);
                if (l < 16) {
                    float bn = q * inv;
                    bbuf[j] = bn;
                    pbuf[cur ^ 1][j] = last ? bn : bn * exc;
                }
                __syncthreads();
                cur ^= 1;
            } else if (!last) {
                if (l < 16) pbuf[cur][j] = bbuf[j] * __expf(em_c);
                __syncthreads();
            }
        }
        if (l < 16) g_bM[b * Lc + j] = bbuf[j];
        if (tid == 0) g_Cb[b] = (float)((double)Ci * 0.6931471805599453);
    }
}

// ---------------------------------------------------------------------------
__global__ void combine(void) {
    int b = blockIdx.x, tid = threadIdx.x;
    float v = g_aM[b * Lc + tid] * g_bM[b * Lc + tid];
#pragma unroll
    for (int o = 16; o > 0; o >>= 1) v += __shfl_xor_sync(0xffffffffu, v, o);
    __shared__ float red[4];
    if ((tid & 31) == 0) red[tid >> 5] = v;
    __syncthreads();
    if (tid == 0)
        g_logz[b] = g_Cf[b] + g_Cb[b] + logf(red[0] + red[1] + red[2] + red[3]);
}

__global__ void final_reduce(float* __restrict__ out) {
    int j = threadIdx.x;
    float v = g_logz[j] - g_score[j];
#pragma unroll
    for (int o = 16; o > 0; o >>= 1) v += __shfl_xor_sync(0xffffffffu, v, o);
    __shared__ float red[4];
    if ((j & 31) == 0) red[j >> 5] = v;
    __syncthreads();
    if (j == 0) out[0] = (red[0] + red[1] + red[2] + red[3]) * (1.0f / (float)Bc);
}

// ---------------------------------------------------------------------------
extern "C" void kernel_launch(void* const* d_in, const int* in_sizes, int n_in,
                              void* d_out, int out_size) {
    const float* em     = (const float*)d_in[0];
    const int*   mask   = (const int*)d_in[1];
    const int*   tags   = (const int*)d_in[2];
    const float* trans  = (const float*)d_in[3];
    const float* startt = (const float*)d_in[4];
    const float* endt   = (const float*)d_in[5];
    (void)in_sizes; (void)n_in; (void)out_size;

    prep_E<<<(Lc * Lc + 255) / 256, 256>>>(trans);
    crf_scan<<<2 * Bc, NT>>>(em, mask, tags, trans, startt, endt);
    combine<<<Bc, Lc>>>();
    final_reduce<<<1, 128>>>((float*)d_out);
}

// round 12
// speedup vs baseline: 2.6184x; 1.0244x over previous
#include <cuda_runtime.h>

#define Lc 128
#define Sc 2048
#define Mh (Sc / 2)               // split: fwd covers t=1..Mh, bwd t=Sc-1..Mh+1
#define Bc 128
#define IGNORE_IDX (-100)
#define NT  256
#define PD  8                     // prefetch depth (power of 2)

__device__ float g_E [Lc * Lc];   // row-major: exp(trans[i][j])
__device__ float g_Et[Lc * Lc];   // transposed
__device__ float g_aM[Bc * Lc];
__device__ float g_bM[Bc * Lc];
__device__ float g_Cf[Bc], g_Cb[Bc];
__device__ float g_logz[Bc];
__device__ float g_score[Bc];

__global__ void prep_E(const float* __restrict__ trans) {
    int idx = blockIdx.x * blockDim.x + threadIdx.x;
    if (idx < Lc * Lc) {
        int i = idx >> 7, j = idx & (Lc - 1);
        float v = expf(trans[idx]);
        g_E[idx] = v;
        g_Et[j * Lc + i] = v;
    }
}

__device__ __forceinline__ void ffma2(unsigned long long& d,
                                      unsigned long long a,
                                      unsigned long long b) {
    asm("fma.rn.f32x2 %0, %1, %2, %0;" : "+l"(d) : "l"(a), "l"(b));
}
__device__ __forceinline__ unsigned long long fadd2(unsigned long long a,
                                                    unsigned long long b) {
    unsigned long long d;
    asm("add.rn.f32x2 %0, %1, %2;" : "=l"(d) : "l"(a), "l"(b));
    return d;
}

// exact power-of-two renorm: r -> (e = floor(log2 r), inv = 2^-e)
__device__ __forceinline__ float exp_strip(float r, int& e_out) {
    unsigned bits = __float_as_uint(r);
    int be = (int)(bits >> 23);
    e_out = be - 127;
    return __uint_as_float((unsigned)(254 - be) << 23);
}

// 64-length dot of smem half vs register-packed E half; full 128-dot via shfl.
__device__ __forceinline__ float dot128(const float* base, int h,
                                        const unsigned long long* Epk) {
    const ulonglong2* p2 = (const ulonglong2*)(base + 64 * h);
    unsigned long long a0 = 0ull, a1 = 0ull, a2 = 0ull, a3 = 0ull;
#pragma unroll
    for (int k = 0; k < 16; k += 2) {
        ulonglong2 pv0 = p2[k];
        ulonglong2 pv1 = p2[k + 1];
        ffma2(a0, pv0.x, Epk[2 * k]);
        ffma2(a1, pv0.y, Epk[2 * k + 1]);
        ffma2(a2, pv1.x, Epk[2 * k + 2]);
        ffma2(a3, pv1.y, Epk[2 * k + 3]);
    }
    unsigned long long sm = fadd2(fadd2(a0, a2), fadd2(a1, a3));
    float q = __uint_as_float((unsigned)sm) +
              __uint_as_float((unsigned)(sm >> 32));
    q += __shfl_xor_sync(0xffffffffu, q, 16);
    return q;
}

// ---------------------------------------------------------------------------
// 2 CTAs per batch: dir 0 = forward (+ gold score), dir 1 = backward.
// warp w lane l: j = 16w + (l&15), h = l>>4. Branch-free step bodies.
// ---------------------------------------------------------------------------
__global__ __launch_bounds__(NT, 2) void crf_scan(
    const float* __restrict__ em,
    const int* __restrict__ mask,
    const int* __restrict__ tags,
    const float* __restrict__ trans,
    const float* __restrict__ startt,
    const float* __restrict__ endt)
{
    const int c   = blockIdx.x;
    const int b   = c >> 1;
    const int dir = c & 1;
    const int tid = threadIdx.x;
    const int w   = tid >> 5;
    const int l   = tid & 31;
    const int j   = (w << 4) | (l & 15);
    const int h   = l >> 4;

    __shared__ __align__(16) float pbuf[2][Lc];
    __shared__ float redf[8];
    __shared__ int   redi[8];

    const int*   tg  = tags + (long long)b * Sc;
    const float* emb = em   + (long long)b * Sc * Lc;
    const int*   mk  = mask + (long long)b * Sc;

    float er[PD];
    int   mr[PD];
    int   Ci  = 0;
    int   cur = 0;

    if (dir == 0) {
        // ---------------- gold-path score ----------------
        float sc = 0.f;
        int lastIdx = -1;
        for (int t = tid; t < Sc; t += NT) {
            int tt = tg[t];
            bool v = (tt != IGNORE_IDX);
            int st = v ? tt : 0;
            if (v && t > lastIdx) lastIdx = t;
            if (t == 0) {
                if (v) sc += startt[st];
            } else if (v) {
                int tp = tg[t - 1];
                int sp = (tp != IGNORE_IDX) ? tp : 0;
                sc += trans[sp * Lc + st] + emb[(long long)t * Lc + st];
            }
        }
#pragma unroll
        for (int o = 16; o > 0; o >>= 1) {
            sc += __shfl_xor_sync(0xffffffffu, sc, o);
            lastIdx = max(lastIdx, __shfl_xor_sync(0xffffffffu, lastIdx, o));
        }
        if (l == 0) { redf[w] = sc; redi[w] = lastIdx; }
        __syncthreads();
        if (tid == 0) {
            float s = 0.f; int li = -1;
#pragma unroll
            for (int k = 0; k < 8; k++) { s += redf[k]; li = max(li, redi[k]); }
            if (li >= 0) {
                int lt = tg[li];
                s += endt[(lt != IGNORE_IDX) ? lt : 0];
            }
            g_score[b] = s;
        }

        unsigned long long Epk[32];
        {
            const ulonglong2* e2 = (const ulonglong2*)(g_Et + j * Lc + 64 * h);
#pragma unroll
            for (int k = 0; k < 16; k++) {
                ulonglong2 v = e2[k];
                Epk[2 * k] = v.x; Epk[2 * k + 1] = v.y;
            }
        }

        float pj = __expf(startt[j] + emb[j]);   // own state (uniform in h-pair)
        __syncthreads();
        if (l < 16) pbuf[0][j] = pj;
        __syncthreads();

#pragma unroll
        for (int d = 0; d < PD; d++) {
            er[d] = emb[(long long)(1 + d) * Lc + j];
            mr[d] = mk[1 + d];
        }
        const float* emp = emb + (long long)(1 + PD) * Lc + j;
        const int*   mkp = mk + 1 + PD;

#pragma unroll 8
        for (int t = 1; t <= Mh; ++t) {
            const int s = (t - 1) & (PD - 1);
            float em_c = er[s];
            int   m    = mr[s];
            er[s] = *emp;  emp += Lc;            // t+PD <= Mh+PD < Sc: in range
            mr[s] = *mkp;  ++mkp;

            int e;
            float inv = exp_strip(pbuf[cur][0], e);
            Ci += m ? e : 0;
            float sfac = __expf(em_c) * inv;
            float q = dot128(pbuf[cur], h, Epk);
            float cand = q * sfac;
            pj = m ? cand : pj;
            if (l < 16) pbuf[cur ^ 1][j] = pj;
            __syncthreads();
            cur ^= 1;
        }
        if (l < 16) g_aM[b * Lc + j] = pj;
        if (tid == 0) g_Cf[b] = (float)((double)Ci * 0.6931471805599453);

    } else {
        unsigned long long Epk[32];
        {
            const ulonglong2* e2 = (const ulonglong2*)(g_E + j * Lc + 64 * h);
#pragma unroll
            for (int k = 0; k < 16; k++) {
                ulonglong2 v = e2[k];
                Epk[2 * k] = v.x; Epk[2 * k + 1] = v.y;
            }
        }

        // init at t = Sc-1: beta = exp(end), d = exp(em_{Sc-1}) * beta
        float bj = __expf(endt[j]);
        __syncthreads();
        if (l < 16)
            pbuf[0][j] = __expf(emb[(long long)(Sc - 1) * Lc + j]) * bj;
        __syncthreads();

#pragma unroll
        for (int d = 0; d < PD; d++) {
            er[d] = emb[(long long)(Sc - 2 - d) * Lc + j];
            mr[d] = mk[Sc - 1 - d];
        }
        const float* emp = emb + (long long)(Sc - 2 - PD) * Lc + j;
        const int*   mkp = mk + (Sc - 1 - PD);

#pragma unroll 8
        for (int s = 0; s < Mh - 1; ++s) {       // t = Sc-1-s down to Mh+1
            const int sl = s & (PD - 1);
            float em_c = er[sl];                  // em_{t-1}
            int   m    = mr[sl];                  // mask_t
            er[sl] = *emp;  emp -= Lc;            // tp = Sc-2-(s+PD) >= 0
            mr[sl] = *mkp;  --mkp;

            int e;
            float inv = exp_strip(pbuf[cur][0], e);
            Ci += m ? e : 0;
            float exc = __expf(em_c);
            float q = dot128(pbuf[cur], h, Epk);
            float bn = m ? q * inv : bj;          // new beta_{t-1}
            bj = bn;
            if (l < 16) pbuf[cur ^ 1][j] = bn * exc;   // d for next step
            __syncthreads();
            cur ^= 1;
        }
        if (l < 16) g_bM[b * Lc + j] = bj;        // beta at t = Mh
        if (tid == 0) g_Cb[b] = (float)((double)Ci * 0.6931471805599453);
    }
}

// ---------------------------------------------------------------------------
__global__ void combine(void) {
    int b = blockIdx.x, tid = threadIdx.x;
    float v = g_aM[b * Lc + tid] * g_bM[b * Lc + tid];
#pragma unroll
    for (int o = 16; o > 0; o >>= 1) v += __shfl_xor_sync(0xffffffffu, v, o);
    __shared__ float red[4];
    if ((tid & 31) == 0) red[tid >> 5] = v;
    __syncthreads();
    if (tid == 0)
        g_logz[b] = g_Cf[b] + g_Cb[b] + logf(red[0] + red[1] + red[2] + red[3]);
}

__global__ void final_reduce(float* __restrict__ out) {
    int j = threadIdx.x;
    float v = g_logz[j] - g_score[j];
#pragma unroll
    for (int o = 16; o > 0; o >>= 1) v += __shfl_xor_sync(0xffffffffu, v, o);
    __shared__ float red[4];
    if ((j & 31) == 0) red[j >> 5] = v;
    __syncthreads();
    if (j == 0) out[0] = (red[0] + red[1] + red[2] + red[3]) * (1.0f / (float)Bc);
}

// ---------------------------------------------------------------------------
extern "C" void kernel_launch(void* const* d_in, const int* in_sizes, int n_in,
                              void* d_out, int out_size) {
    const float* em     = (const float*)d_in[0];
    const int*   mask   = (const int*)d_in[1];
    const int*   tags   = (const int*)d_in[2];
    const float* trans  = (const float*)d_in[3];
    const float* startt = (const float*)d_in[4];
    const float* endt   = (const float*)d_in[5];
    (void)in_sizes; (void)n_in; (void)out_size;

    prep_E<<<(Lc * Lc + 255) / 256, 256>>>(trans);
    crf_scan<<<2 * Bc, NT>>>(em, mask, tags, trans, startt, endt);
    combine<<<Bc, Lc>>>();
    final_reduce<<<1, 128>>>((float*)d_out);
}

// round 14
// speedup vs baseline: 2.7889x; 1.0651x over previous
#include <cuda_runtime.h>

#define Lc 128
#define Sc 2048
#define Mh (Sc / 2)               // split: fwd covers t=1..Mh, bwd t=Sc-1..Mh+1
#define Bc 128
#define IGNORE_IDX (-100)
#define NT  256
#define PD  8                     // prefetch depth (power of 2)

__device__ float g_E [Lc * Lc];   // row-major: exp(trans[i][j])
__device__ float g_Et[Lc * Lc];   // transposed
__device__ float g_logz[Bc];
__device__ float g_score[Bc];

__global__ void prep_E(const float* __restrict__ trans) {
    int idx = blockIdx.x * blockDim.x + threadIdx.x;
    if (idx < Lc * Lc) {
        int i = idx >> 7, j = idx & (Lc - 1);
        float v = expf(trans[idx]);
        g_E[idx] = v;
        g_Et[j * Lc + i] = v;
    }
}

__device__ __forceinline__ void ffma2(unsigned long long& d,
                                      unsigned long long a,
                                      unsigned long long b) {
    asm("fma.rn.f32x2 %0, %1, %2, %0;" : "+l"(d) : "l"(a), "l"(b));
}
__device__ __forceinline__ unsigned long long fadd2(unsigned long long a,
                                                    unsigned long long b) {
    unsigned long long d;
    asm("add.rn.f32x2 %0, %1, %2;" : "=l"(d) : "l"(a), "l"(b));
    return d;
}

// exact power-of-two renorm: r -> (e = floor(log2 r), inv = 2^-e)
__device__ __forceinline__ float exp_strip(float r, int& e_out) {
    unsigned bits = __float_as_uint(r);
    int be = (int)(bits >> 23);
    e_out = be - 127;
    return __uint_as_float((unsigned)(254 - be) << 23);
}

// full 128-length dot of smem vector vs register-packed E column/row.
__device__ __forceinline__ float dot128f(const float* base,
                                         const unsigned long long* Epk) {
    const ulonglong2* p2 = (const ulonglong2*)base;
    unsigned long long a0 = 0ull, a1 = 0ull, a2 = 0ull, a3 = 0ull;
#pragma unroll
    for (int k = 0; k < 32; k += 2) {
        ulonglong2 pv0 = p2[k];
        ulonglong2 pv1 = p2[k + 1];
        ffma2(a0, pv0.x, Epk[2 * k]);
        ffma2(a1, pv0.y, Epk[2 * k + 1]);
        ffma2(a2, pv1.x, Epk[2 * k + 2]);
        ffma2(a3, pv1.y, Epk[2 * k + 3]);
    }
    unsigned long long sm = fadd2(fadd2(a0, a2), fadd2(a1, a3));
    return __uint_as_float((unsigned)sm) +
           __uint_as_float((unsigned)(sm >> 32));
}

// ---------------------------------------------------------------------------
// ONE CTA per batch (128 CTAs -> <=1 per SM, uniform load).
// Group 0 (tid 0-127): forward scan + gold score. Group 1 (tid 128-255):
// backward scan. Independent named barriers; final in-CTA combine.
// ---------------------------------------------------------------------------
__global__ __launch_bounds__(NT, 1) void crf_scan(
    const float* __restrict__ em,
    const int* __restrict__ mask,
    const int* __restrict__ tags,
    const float* __restrict__ trans,
    const float* __restrict__ startt,
    const float* __restrict__ endt)
{
    const int b    = blockIdx.x;
    const int tid  = threadIdx.x;
    const int g    = tid >> 7;        // 0 = fwd, 1 = bwd
    const int j    = tid & (Lc - 1);  // state index within group
    const int l    = tid & 31;

    __shared__ __align__(16) float pbufF[2][Lc];
    __shared__ __align__(16) float pbufB[2][Lc];
    __shared__ float aMs[Lc], bMs[Lc];
    __shared__ float redf[4];
    __shared__ int   redi[4];
    __shared__ int   CiS[2];

#define GBAR() asm volatile("bar.sync %0, 128;" :: "r"(g + 1) : "memory")

    const int*   tg  = tags + (long long)b * Sc;
    const float* emb = em   + (long long)b * Sc * Lc;
    const int*   mk  = mask + (long long)b * Sc;

    float er[PD];
    int   mr[PD];
    int   Ci  = 0;
    int   cur = 0;

    if (g == 0) {
        // ---------------- gold-path score (128 threads, 16 iters) ----------
        float sc = 0.f;
        int lastIdx = -1;
        for (int t = j; t < Sc; t += Lc) {
            int tt = tg[t];
            bool v = (tt != IGNORE_IDX);
            int st = v ? tt : 0;
            if (v && t > lastIdx) lastIdx = t;
            if (t == 0) {
                if (v) sc += startt[st];
            } else if (v) {
                int tp = tg[t - 1];
                int sp = (tp != IGNORE_IDX) ? tp : 0;
                sc += trans[sp * Lc + st] + emb[(long long)t * Lc + st];
            }
        }
#pragma unroll
        for (int o = 16; o > 0; o >>= 1) {
            sc += __shfl_xor_sync(0xffffffffu, sc, o);
            lastIdx = max(lastIdx, __shfl_xor_sync(0xffffffffu, lastIdx, o));
        }
        if (l == 0) { redf[tid >> 5] = sc; redi[tid >> 5] = lastIdx; }
        GBAR();
        if (tid == 0) {
            float s = redf[0] + redf[1] + redf[2] + redf[3];
            int li = max(max(redi[0], redi[1]), max(redi[2], redi[3]));
            if (li >= 0) {
                int lt = tg[li];
                s += endt[(lt != IGNORE_IDX) ? lt : 0];
            }
            g_score[b] = s;
        }

        // full E column j (transposed layout)
        unsigned long long Epk[64];
        {
            const ulonglong2* e2 = (const ulonglong2*)(g_Et + j * Lc);
#pragma unroll
            for (int k = 0; k < 32; k++) {
                ulonglong2 v = e2[k];
                Epk[2 * k] = v.x; Epk[2 * k + 1] = v.y;
            }
        }

        float pj = __expf(startt[j] + emb[j]);
        pbufF[0][j] = pj;
        GBAR();

#pragma unroll
        for (int d = 0; d < PD; d++) {
            er[d] = emb[(long long)(1 + d) * Lc + j];
            mr[d] = mk[1 + d];
        }
        const float* emp = emb + (long long)(1 + PD) * Lc + j;
        const int*   mkp = mk + 1 + PD;

#pragma unroll 8
        for (int t = 1; t <= Mh; ++t) {
            const int s = (t - 1) & (PD - 1);
            float em_c = er[s];
            int   m    = mr[s];
            er[s] = *emp;  emp += Lc;            // t+PD <= Mh+PD < Sc
            mr[s] = *mkp;  ++mkp;

            int e;
            float inv = exp_strip(pbufF[cur][0], e);
            Ci += m ? e : 0;
            float sfac = __expf(em_c) * inv;
            float q = dot128f(pbufF[cur], Epk);
            pj = m ? q * sfac : pj;
            pbufF[cur ^ 1][j] = pj;
            GBAR();
            cur ^= 1;
        }
        aMs[j] = pj;
        if (tid == 0) CiS[0] = Ci;

    } else {
        // full E row j (row-major layout)
        unsigned long long Epk[64];
        {
            const ulonglong2* e2 = (const ulonglong2*)(g_E + j * Lc);
#pragma unroll
            for (int k = 0; k < 32; k++) {
                ulonglong2 v = e2[k];
                Epk[2 * k] = v.x; Epk[2 * k + 1] = v.y;
            }
        }

        // init at t = Sc-1: beta = exp(end), d = exp(em_{Sc-1}) * beta
        float bj = __expf(endt[j]);
        pbufB[0][j] = __expf(emb[(long long)(Sc - 1) * Lc + j]) * bj;
        GBAR();

#pragma unroll
        for (int d = 0; d < PD; d++) {
            er[d] = emb[(long long)(Sc - 2 - d) * Lc + j];
            mr[d] = mk[Sc - 1 - d];
        }
        const float* emp = emb + (long long)(Sc - 2 - PD) * Lc + j;
        const int*   mkp = mk + (Sc - 1 - PD);

#pragma unroll 8
        for (int s = 0; s < Mh - 1; ++s) {       // t = Sc-1-s down to Mh+1
            const int sl = s & (PD - 1);
            float em_c = er[sl];                  // em_{t-1}
            int   m    = mr[sl];                  // mask_t
            er[sl] = *emp;  emp -= Lc;            // tp >= 1016 >= 0
            mr[sl] = *mkp;  --mkp;

            int e;
            float inv = exp_strip(pbufB[cur][0], e);
            Ci += m ? e : 0;
            float exc = __expf(em_c);
            float q = dot128f(pbufB[cur], Epk);
            float bn = m ? q * inv : bj;
            bj = bn;
            pbufB[cur ^ 1][j] = bn * exc;
            GBAR();
            cur ^= 1;
        }
        bMs[j] = bj;                              // beta at t = Mh
        if (j == 0) CiS[1] = Ci;
    }

    // ---------------- in-CTA combine ----------------
    __syncthreads();
    if (g == 0) {
        float v = aMs[j] * bMs[j];
#pragma unroll
        for (int o = 16; o > 0; o >>= 1) v += __shfl_xor_sync(0xffffffffu, v, o);
        if (l == 0) redf[tid >> 5] = v;
        GBAR();
        if (tid == 0) {
            double Csum = (double)(CiS[0] + CiS[1]) * 0.6931471805599453;
            g_logz[b] = (float)(Csum +
                (double)logf(redf[0] + redf[1] + redf[2] + redf[3]));
        }
    }
#undef GBAR
}

// ---------------------------------------------------------------------------
__global__ void final_reduce(float* __restrict__ out) {
    int j = threadIdx.x;
    float v = g_logz[j] - g_score[j];
#pragma unroll
    for (int o = 16; o > 0; o >>= 1) v += __shfl_xor_sync(0xffffffffu, v, o);
    __shared__ float red[4];
    if ((j & 31) == 0) red[j >> 5] = v;
    __syncthreads();
    if (j == 0) out[0] = (red[0] + red[1] + red[2] + red[3]) * (1.0f / (float)Bc);
}

// ---------------------------------------------------------------------------
extern "C" void kernel_launch(void* const* d_in, const int* in_sizes, int n_in,
                              void* d_out, int out_size) {
    const float* em     = (const float*)d_in[0];
    const int*   mask   = (const int*)d_in[1];
    const int*   tags   = (const int*)d_in[2];
    const float* trans  = (const float*)d_in[3];
    const float* startt = (const float*)d_in[4];
    const float* endt   = (const float*)d_in[5];
    (void)in_sizes; (void)n_in; (void)out_size;

    prep_E<<<(Lc * Lc + 255) / 256, 256>>>(trans);
    crf_scan<<<Bc, NT>>>(em, mask, tags, trans, startt, endt);
    final_reduce<<<1, 128>>>((float*)d_out);
}

// round 15
// speedup vs baseline: 2.8920x; 1.0370x over previous
#include <cuda_runtime.h>

#define Lc 128
#define Sc 2048
#define Mh (Sc / 2)               // split: fwd covers t=1..Mh, bwd t=Sc-1..Mh+1
#define Bc 128
#define IGNORE_IDX (-100)
#define NT  256
#define PD  8                     // prefetch depth (power of 2)

__device__ float g_E [Lc * Lc];   // row-major: exp(trans[i][j])
__device__ float g_Et[Lc * Lc];   // transposed
__device__ float g_logz[Bc];
__device__ float g_score[Bc];

__global__ void prep_E(const float* __restrict__ trans) {
    int idx = blockIdx.x * blockDim.x + threadIdx.x;
    if (idx < Lc * Lc) {
        int i = idx >> 7, j = idx & (Lc - 1);
        float v = expf(trans[idx]);
        g_E[idx] = v;
        g_Et[j * Lc + i] = v;
    }
}

__device__ __forceinline__ void ffma2(unsigned long long& d,
                                      unsigned long long a,
                                      unsigned long long b) {
    asm("fma.rn.f32x2 %0, %1, %2, %0;" : "+l"(d) : "l"(a), "l"(b));
}
__device__ __forceinline__ unsigned long long fadd2(unsigned long long a,
                                                    unsigned long long b) {
    unsigned long long d;
    asm("add.rn.f32x2 %0, %1, %2;" : "=l"(d) : "l"(a), "l"(b));
    return d;
}

// exact power-of-two renorm: r -> (e = floor(log2 r), inv = 2^-e)
__device__ __forceinline__ float exp_strip(float r, int& e_out) {
    unsigned bits = __float_as_uint(r);
    int be = (int)(bits >> 23);
    e_out = be - 127;
    return __uint_as_float((unsigned)(254 - be) << 23);
}

// full 128-length dot of smem vector vs register-packed E column/row.
__device__ __forceinline__ float dot128f(const float* base,
                                         const unsigned long long* Epk) {
    const ulonglong2* p2 = (const ulonglong2*)base;
    unsigned long long a0 = 0ull, a1 = 0ull, a2 = 0ull, a3 = 0ull;
#pragma unroll
    for (int k = 0; k < 32; k += 2) {
        ulonglong2 pv0 = p2[k];
        ulonglong2 pv1 = p2[k + 1];
        ffma2(a0, pv0.x, Epk[2 * k]);
        ffma2(a1, pv0.y, Epk[2 * k + 1]);
        ffma2(a2, pv1.x, Epk[2 * k + 2]);
        ffma2(a3, pv1.y, Epk[2 * k + 3]);
    }
    unsigned long long sm = fadd2(fadd2(a0, a2), fadd2(a1, a3));
    return __uint_as_float((unsigned)sm) +
           __uint_as_float((unsigned)(sm >> 32));
}

// ---------------------------------------------------------------------------
// ONE CTA per batch (128 CTAs -> <=1 per SM, uniform load).
// Group 0 (tid 0-127): forward scan + gold score. Group 1: backward scan.
// Renorm every 4th step; exc/exp pipelined one step ahead; refills post-tail.
// ---------------------------------------------------------------------------
__global__ __launch_bounds__(NT, 1) void crf_scan(
    const float* __restrict__ em,
    const int* __restrict__ mask,
    const int* __restrict__ tags,
    const float* __restrict__ trans,
    const float* __restrict__ startt,
    const float* __restrict__ endt)
{
    const int b    = blockIdx.x;
    const int tid  = threadIdx.x;
    const int g    = tid >> 7;        // 0 = fwd, 1 = bwd
    const int j    = tid & (Lc - 1);  // state index within group
    const int l    = tid & 31;

    __shared__ __align__(16) float pbufF[2][Lc];
    __shared__ __align__(16) float pbufB[2][Lc];
    __shared__ float aMs[Lc], bMs[Lc];
    __shared__ float redf[4];
    __shared__ int   redi[4];
    __shared__ int   CiS[2];

#define GBAR() asm volatile("bar.sync %0, 128;" :: "r"(g + 1) : "memory")

    const int*   tg  = tags + (long long)b * Sc;
    const float* emb = em   + (long long)b * Sc * Lc;
    const int*   mk  = mask + (long long)b * Sc;

    float er[PD];
    int   mr[PD];
    int   Ci  = 0;
    int   cur = 0;

    if (g == 0) {
        // ---------------- gold-path score (128 threads, 16 iters) ----------
        float sc = 0.f;
        int lastIdx = -1;
        for (int t = j; t < Sc; t += Lc) {
            int tt = tg[t];
            bool v = (tt != IGNORE_IDX);
            int st = v ? tt : 0;
            if (v && t > lastIdx) lastIdx = t;
            if (t == 0) {
                if (v) sc += startt[st];
            } else if (v) {
                int tp = tg[t - 1];
                int sp = (tp != IGNORE_IDX) ? tp : 0;
                sc += trans[sp * Lc + st] + emb[(long long)t * Lc + st];
            }
        }
#pragma unroll
        for (int o = 16; o > 0; o >>= 1) {
            sc += __shfl_xor_sync(0xffffffffu, sc, o);
            lastIdx = max(lastIdx, __shfl_xor_sync(0xffffffffu, lastIdx, o));
        }
        if (l == 0) { redf[tid >> 5] = sc; redi[tid >> 5] = lastIdx; }
        GBAR();
        if (tid == 0) {
            float s = redf[0] + redf[1] + redf[2] + redf[3];
            int li = max(max(redi[0], redi[1]), max(redi[2], redi[3]));
            if (li >= 0) {
                int lt = tg[li];
                s += endt[(lt != IGNORE_IDX) ? lt : 0];
            }
            g_score[b] = s;
        }

        // full E column j (transposed layout)
        unsigned long long Epk[64];
        {
            const ulonglong2* e2 = (const ulonglong2*)(g_Et + j * Lc);
#pragma unroll
            for (int k = 0; k < 32; k++) {
                ulonglong2 v = e2[k];
                Epk[2 * k] = v.x; Epk[2 * k + 1] = v.y;
            }
        }

        float pj = __expf(startt[j] + emb[j]);
        pbufF[0][j] = pj;

#pragma unroll
        for (int d = 0; d < PD; d++) {
            er[d] = emb[(long long)(1 + d) * Lc + j];
            mr[d] = mk[1 + d];
        }
        const float* emp = emb + (long long)(1 + PD) * Lc + j;
        const int*   mkp = mk + 1 + PD;
        float exc_cur = __expf(er[0]);            // exp(em_1)
        GBAR();

#pragma unroll 8
        for (int t = 1; t <= Mh; ++t) {
            const int s = (t - 1) & (PD - 1);
            const int m = mr[s];
            float sfac = exc_cur;
            if ((t & 3) == 1) {                   // renorm every 4th step
                int e;
                float inv = exp_strip(pbufF[cur][0], e);
                Ci += m ? e : 0;
                sfac = exc_cur * inv;
            }
            float q = dot128f(pbufF[cur], Epk);
            pj = m ? q * sfac : pj;
            pbufF[cur ^ 1][j] = pj;
            // tail: refill + next exp overlap the barrier wait
            er[s] = *emp;  emp += Lc;             // t+PD <= Mh+PD < Sc
            mr[s] = *mkp;  ++mkp;
            exc_cur = __expf(er[t & (PD - 1)]);   // exp(em_{t+1})
            GBAR();
            cur ^= 1;
        }
        aMs[j] = pj;
        if (tid == 0) CiS[0] = Ci;

    } else {
        // full E row j (row-major layout)
        unsigned long long Epk[64];
        {
            const ulonglong2* e2 = (const ulonglong2*)(g_E + j * Lc);
#pragma unroll
            for (int k = 0; k < 32; k++) {
                ulonglong2 v = e2[k];
                Epk[2 * k] = v.x; Epk[2 * k + 1] = v.y;
            }
        }

        // init at t = Sc-1: beta = exp(end), d = exp(em_{Sc-1}) * beta
        float bj = __expf(endt[j]);
        pbufB[0][j] = __expf(emb[(long long)(Sc - 1) * Lc + j]) * bj;

#pragma unroll
        for (int d = 0; d < PD; d++) {
            er[d] = emb[(long long)(Sc - 2 - d) * Lc + j];
            mr[d] = mk[Sc - 1 - d];
        }
        const float* emp = emb + (long long)(Sc - 2 - PD) * Lc + j;
        const int*   mkp = mk + (Sc - 1 - PD);
        float exc_cur = __expf(er[0]);            // exp(em_{Sc-2})
        GBAR();

#pragma unroll 8
        for (int s = 0; s < Mh - 1; ++s) {        // t = Sc-1-s down to Mh+1
            const int sl = s & (PD - 1);
            const int m = mr[sl];                 // mask_t
            float inv = 1.0f;
            if ((s & 3) == 0) {                   // renorm every 4th step
                int e;
                inv = exp_strip(pbufB[cur][0], e);
                Ci += m ? e : 0;
            }
            float q = dot128f(pbufB[cur], Epk);
            float bn = m ? ((s & 3) == 0 ? q * inv : q) : bj;
            bj = bn;
            pbufB[cur ^ 1][j] = bn * exc_cur;     // exc_cur = exp(em_{t-1})
            // tail: refill + next exp overlap the barrier wait
            er[sl] = *emp;  emp -= Lc;            // tp >= 1016 >= 0
            mr[sl] = *mkp;  --mkp;
            exc_cur = __expf(er[(s + 1) & (PD - 1)]);  // exp(em_{t-2})
            GBAR();
            cur ^= 1;
        }
        bMs[j] = bj;                              // beta at t = Mh
        if (j == 0) CiS[1] = Ci;
    }

    // ---------------- in-CTA combine ----------------
    __syncthreads();
    if (g == 0) {
        float v = aMs[j] * bMs[j];
#pragma unroll
        for (int o = 16; o > 0; o >>= 1) v += __shfl_xor_sync(0xffffffffu, v, o);
        if (l == 0) redf[tid >> 5] = v;
        GBAR();
        if (tid == 0) {
            double Csum = (double)(CiS[0] + CiS[1]) * 0.6931471805599453;
            g_logz[b] = (float)(Csum +
                (double)logf(redf[0] + redf[1] + redf[2] + redf[3]));
        }
    }
#undef GBAR
}

// ---------------------------------------------------------------------------
__global__ void final_reduce(float* __restrict__ out) {
    int j = threadIdx.x;
    float v = g_logz[j] - g_score[j];
#pragma unroll
    for (int o = 16; o > 0; o >>= 1) v += __shfl_xor_sync(0xffffffffu, v, o);
    __shared__ float red[4];
    if ((j & 31) == 0) red[j >> 5] = v;
    __syncthreads();
    if (j == 0) out[0] = (red[0] + red[1] + red[2] + red[3]) * (1.0f / (float)Bc);
}

// ---------------------------------------------------------------------------
extern "C" void kernel_launch(void* const* d_in, const int* in_sizes, int n_in,
                              void* d_out, int out_size) {
    const float* em     = (const float*)d_in[0];
    const int*   mask   = (const int*)d_in[1];
    const int*   tags   = (const int*)d_in[2];
    const float* trans  = (const float*)d_in[3];
    const float* startt = (const float*)d_in[4];
    const float* endt   = (const float*)d_in[5];
    (void)in_sizes; (void)n_in; (void)out_size;

    prep_E<<<(Lc * Lc + 255) / 256, 256>>>(trans);
    crf_scan<<<Bc, NT>>>(em, mask, tags, trans, startt, endt);
    final_reduce<<<1, 128>>>((float*)d_out);
}